// round 11
// baseline (speedup 1.0000x reference)
#include <cuda_runtime.h>
#include <cstdint>

// Problem constants (Pose_Loss: B=65536, D=154)
#define BB   65536
#define DD   154
#define N4   ((BB * DD) / 4)        // 2,523,136 float4s per array

#define BLOCK_THREADS 256
#define T4   256                    // float4s per array per tile (1/thread)
#define NTILES (N4 / T4)            // 9856 tiles
static_assert(N4 % T4 == 0, "tile must divide N4");

#define TILE_BYTES  (T4 * 16)           // 4096 B per array
#define STAGE_BYTES (2 * TILE_BYTES)    // 8192 B per stage (rl + rr via TMA)
#define STAGES 4
#define LOOKAHEAD (STAGES - 1)          // 3 outstanding TMA stage-groups

#define GRID_BLOCKS 448                 // 9856 / 448 = exactly 22 tiles/block
static_assert(NTILES % GRID_BLOCKS == 0, "perfect balance");

#define MBAR_OFF (STAGES * STAGE_BYTES)
#define DYN_SMEM (MBAR_OFF + STAGES * 8)   // 32 KB + mbarriers

// Scratch (allocation-free device globals; zero at load, re-zeroed each exec)
__device__ double        g_acc[2];   // [0]=recon, [1]=KLD
__device__ int           g_count;
__device__ unsigned int  g_done;

__device__ __forceinline__ unsigned smem_u32(const void* p) {
    unsigned a;
    asm("{ .reg .u64 t; cvta.to.shared.u64 t, %1; cvt.u32.u64 %0, t; }"
        : "=r"(a) : "l"(p));
    return a;
}

__device__ __forceinline__ void mbar_init(unsigned mbar, unsigned count) {
    asm volatile("mbarrier.init.shared.b64 [%0], %1;"
                 :: "r"(mbar), "r"(count) : "memory");
}

__device__ __forceinline__ void mbar_expect_tx(unsigned mbar, unsigned bytes) {
    asm volatile("mbarrier.arrive.expect_tx.shared.b64 _, [%0], %1;"
                 :: "r"(mbar), "r"(bytes) : "memory");
}

__device__ __forceinline__ void bulk_ldg(unsigned dst_smem, const void* src,
                                         unsigned bytes, unsigned mbar) {
    asm volatile(
        "cp.async.bulk.shared::cluster.global.mbarrier::complete_tx::bytes "
        "[%0], [%1], %2, [%3];"
        :: "r"(dst_smem), "l"(src), "r"(bytes), "r"(mbar) : "memory");
}

__device__ __forceinline__ void mbar_wait(unsigned mbar, unsigned parity) {
    asm volatile(
        "{\n\t"
        ".reg .pred P;\n\t"
        "W%=:\n\t"
        "mbarrier.try_wait.parity.acquire.cta.shared::cta.b64 P, [%0], %1, 0x989680;\n\t"
        "@P bra D%=;\n\t"
        "bra W%=;\n\t"
        "D%=:\n\t"
        "}"
        :: "r"(mbar), "r"(parity) : "memory");
}

__device__ __forceinline__ float2 row_weights(int l, int f) {
    // lr in {0,1,2}: use_l <=> l != 1 ; use_r <=> l != 0 ; gated by f != -1
    bool valid = (f != -1);
    return make_float2((valid && l != 1) ? 1.0f : 0.0f,
                       (valid && l != 0) ? 1.0f : 0.0f);
}

__global__ void __launch_bounds__(BLOCK_THREADS, 3)
fused_pose_loss(const char* __restrict__ rl, const char* __restrict__ rr,
                const float4* __restrict__ kl, const float4* __restrict__ kr,
                const int* __restrict__ lr,  const int* __restrict__ fpose,
                float* __restrict__ out, int out_size) {
    extern __shared__ __align__(16) char dynsmem[];
    const unsigned sbase = smem_u32(dynsmem);

    const int tid  = threadIdx.x;
    const unsigned gtid = blockIdx.x * BLOCK_THREADS + tid;

    if (tid == 0) {
        #pragma unroll
        for (int s = 0; s < STAGES; s++)
            mbar_init(sbase + MBAR_OFF + s * 8, 1);
    }
    __syncthreads();

    const unsigned stride = gridDim.x;            // 448
    const unsigned t0 = blockIdx.x;

    // TMA stage issue: rl + rr only
    auto issue = [&](unsigned tile, int stage) {
        unsigned mb  = sbase + MBAR_OFF + stage * 8;
        unsigned dst = sbase + stage * STAGE_BYTES;
        size_t off = (size_t)tile * TILE_BYTES;
        mbar_expect_tx(mb, STAGE_BYTES);
        bulk_ldg(dst,              rl + off, TILE_BYTES, mb);
        bulk_ldg(dst + TILE_BYTES, rr + off, TILE_BYTES, mb);
    };

    // prime TMA pipeline: stages 0..2
    if (tid == 0) {
        #pragma unroll
        for (int s = 0; s < LOOKAHEAD; s++) {
            unsigned tile = t0 + s * stride;
            if (tile < NTILES) issue(tile, s);
        }
    }

    // ---- Phase A: per-row count (448*256 = 114,688 threads > BB).
    // Issued after TMA prime so it overlaps the first transfers.
    int c = 0;
    if (gtid < BB) {
        int l = lr[gtid];
        if (fpose[gtid] != -1)
            c = (l != 1 ? 1 : 0) + (l != 0 ? 1 : 0);
    }

    // LDG prefetch of KLD pair for the first tile (registers)
    float4 c_cur = kl[t0 * T4 + tid];
    float4 d_cur = kr[t0 * T4 + tid];

    double racc = 0.0, kacc = 0.0;
    int k = 0;

    for (unsigned t = t0; t < NTILES; t += stride, k++) {
        // TMA refill 3 tiles ahead (buffer reuse guarded by prev syncthreads)
        unsigned nt = t + LOOKAHEAD * stride;
        if (tid == 0 && nt < NTILES)
            issue(nt, (k + LOOKAHEAD) & (STAGES - 1));

        // LDG prefetch of KLD pair for the NEXT tile (one-iteration cover)
        unsigned tn = t + stride;
        float4 c_nxt, d_nxt;
        if (tn < NTILES) {
            c_nxt = kl[tn * T4 + tid];
            d_nxt = kr[tn * T4 + tid];
        }

        // row resolution + weights (L2-resident; hidden under TMA wait)
        unsigned i    = t * T4 + tid;
        unsigned base = i * 4u;
        unsigned row0 = base / DD;               // udiv -> mul-hi
        unsigned rem  = base - row0 * DD;
        float2 w0 = row_weights(lr[row0], fpose[row0]);
        bool straddle = (rem > (unsigned)(DD - 4));
        float2 w1 = w0;
        if (straddle)
            w1 = row_weights(lr[row0 + 1], fpose[row0 + 1]);

        // wait for this stage's TMA data (recon pair)
        int stage = k & (STAGES - 1);
        mbar_wait(sbase + MBAR_OFF + stage * 8, (k >> 2) & 1);

        const float4* sb = (const float4*)(dynsmem + stage * STAGE_BYTES);
        float4 a = sb[tid];         // recon_l
        float4 b = sb[T4 + tid];    // recon_r

        float rt, kt;
        if (!straddle) {
            rt = w0.x * ((a.x + a.y) + (a.z + a.w))
               + w0.y * ((b.x + b.y) + (b.z + b.w));
            kt = w0.x * ((c_cur.x + c_cur.y) + (c_cur.z + c_cur.w))
               + w0.y * ((d_cur.x + d_cur.y) + (d_cur.z + d_cur.w));
        } else {
            float ae[4] = {a.x, a.y, a.z, a.w};
            float be[4] = {b.x, b.y, b.z, b.w};
            float ce[4] = {c_cur.x, c_cur.y, c_cur.z, c_cur.w};
            float de[4] = {d_cur.x, d_cur.y, d_cur.z, d_cur.w};
            rt = 0.0f; kt = 0.0f;
            #pragma unroll
            for (int e = 0; e < 4; e++) {
                float2 w = ((rem + e) >= (unsigned)DD) ? w1 : w0;
                rt += w.x * ae[e] + w.y * be[e];
                kt += w.x * ce[e] + w.y * de[e];
            }
        }
        racc += (double)rt;
        kacc += (double)kt;

        c_cur = c_nxt;
        d_cur = d_nxt;

        __syncthreads();   // all threads done reading this TMA stage
    }

    // ---- Phase C: block reduction ----
    #pragma unroll
    for (int off = 16; off > 0; off >>= 1) {
        racc += __shfl_down_sync(0xFFFFFFFFu, racc, off);
        kacc += __shfl_down_sync(0xFFFFFFFFu, kacc, off);
        c    += __shfl_down_sync(0xFFFFFFFFu, c,    off);
    }

    __shared__ double s_r[8], s_k[8];
    __shared__ int    s_c[8];
    int wid = threadIdx.x >> 5;
    int lid = threadIdx.x & 31;
    if (lid == 0) { s_r[wid] = racc; s_k[wid] = kacc; s_c[wid] = c; }
    __syncthreads();

    if (wid == 0) {
        int nw = blockDim.x >> 5;
        double br = (lid < nw) ? s_r[lid] : 0.0;
        double bk = (lid < nw) ? s_k[lid] : 0.0;
        int    bc = (lid < nw) ? s_c[lid] : 0;
        #pragma unroll
        for (int off = 4; off > 0; off >>= 1) {
            br += __shfl_down_sync(0xFFFFFFFFu, br, off);
            bk += __shfl_down_sync(0xFFFFFFFFu, bk, off);
            bc += __shfl_down_sync(0xFFFFFFFFu, bc, off);
        }
        if (lid == 0) {
            atomicAdd(&g_acc[0], br);
            atomicAdd(&g_acc[1], bk);
            if (bc) atomicAdd(&g_count, bc);
        }
    }

    // ---- Phase D: last-block finalize + reset ----
    __shared__ bool is_last;
    if (threadIdx.x == 0) {
        __threadfence();
        unsigned tkt = atomicAdd(&g_done, 1u);
        is_last = (tkt == gridDim.x - 1);
    }
    __syncthreads();
    if (is_last && threadIdx.x == 0) {
        __threadfence();
        double vr = g_acc[0];
        double vk = g_acc[1];
        int    vc = g_count;
        if (out_size > 0) out[0] = (float)(vr / 154.0);
        if (out_size > 1) out[1] = (float)vk;
        if (out_size > 2) out[2] = (float)vc;
        g_acc[0] = 0.0;
        g_acc[1] = 0.0;
        g_count  = 0;
        __threadfence();
        g_done   = 0;
    }
}

extern "C" void kernel_launch(void* const* d_in, const int* in_sizes, int n_in,
                              void* d_out, int out_size) {
    const char*   rl = (const char*)d_in[0];
    const char*   rr = (const char*)d_in[1];
    const float4* kl = (const float4*)d_in[2];
    const float4* kr = (const float4*)d_in[3];
    const int* lr    = (const int*)d_in[4];
    const int* fpose = (const int*)d_in[5];
    float* out = (float*)d_out;

    cudaFuncSetAttribute(fused_pose_loss,
                         cudaFuncAttributeMaxDynamicSharedMemorySize, DYN_SMEM);

    fused_pose_loss<<<GRID_BLOCKS, BLOCK_THREADS, DYN_SMEM>>>(
        rl, rr, kl, kr, lr, fpose, out, out_size);
}